// round 1
// baseline (speedup 1.0000x reference)
#include <cuda_runtime.h>
#include <math.h>

#define Bn 16
#define Cn 2048
#define Ln 256
#define EO 16
#define Hn 4
#define Gn 4
#define Nn (Bn*Cn)      /* 32768 */
#define NEn 524288

// ---------------- scratch (device globals; no allocation) ----------------
__device__ float    g_fmean[Bn*Ln];        // per-batch feature mean (x2048)
__device__ float    g_M[Bn*Ln*EO];         // folded emb*SE*gat matrix per batch
__device__ float    g_cb[Bn*EO];           // folded bias
__device__ float    g_feat[Nn*EO];
__device__ float    g_el[Nn*Hn];
__device__ float    g_er[Nn*Hn];
__device__ unsigned g_mord[Nn*Hn];         // ordered-uint segment max
__device__ float    g_den[Nn*Hn];
__device__ float    g_acc[Nn*EO];
__device__ float    g_enc[Nn*EO];
__device__ float    g_pa[Nn];
__device__ float    g_pb[Nn];

__device__ __forceinline__ unsigned f2ord(float f){
    unsigned u = __float_as_uint(f);
    return (u & 0x80000000u) ? ~u : (u | 0x80000000u);
}
__device__ __forceinline__ float ord2f(unsigned u){
    return __uint_as_float((u & 0x80000000u) ? (u & 0x7FFFFFFFu) : ~u);
}

// ---------------- init scratch ----------------
__global__ void k_init(){
    int i = blockIdx.x*256 + threadIdx.x;
    if(i < Bn*Ln) g_fmean[i] = 0.f;
    if(i < Nn*Hn){ g_mord[i] = 0u; g_den[i] = 0.f; }
    if(i < Nn*EO) g_acc[i] = 0.f;
}

// ---------------- per-batch feature mean (pass 1 over feature) ----------------
__global__ void k_fmean(const float* __restrict__ feature){
    int b = blockIdx.y, ch = blockIdx.x, k = threadIdx.x;   // 64 chunks of 32 rows
    const float* p = feature + ((size_t)b*Cn + (size_t)ch*32)*Ln + k;
    float a = 0.f;
    #pragma unroll
    for(int r=0;r<32;r++) a += p[(size_t)r*Ln];
    atomicAdd(&g_fmean[b*Ln + k], a);
}

// ---------------- SE path + build folded matrix M_b ----------------
__global__ void k_prep(const float* __restrict__ embW, const float* __restrict__ embB,
                       const float* __restrict__ w1,   const float* __restrict__ b1,
                       const float* __restrict__ w2,   const float* __restrict__ b2,
                       const float* __restrict__ gatW){
    int b = blockIdx.x, t = threadIdx.x;
    __shared__ float zs[EO], r1[4], ss[EO], sgw[EO*EO];
    if(t < EO*EO) sgw[t] = gatW[t];
    if(t < EO){
        float a = embB[t];
        const float* fm = &g_fmean[b*Ln];
        for(int k=0;k<Ln;k++) a = fmaf(fm[k]*(1.0f/Cn), embW[t*Ln+k], a);
        zs[t] = a;
    }
    __syncthreads();
    if(t < 4){
        float a = b1[t];
        #pragma unroll
        for(int e=0;e<EO;e++) a = fmaf(w1[t*EO+e], zs[e], a);
        r1[t] = fmaxf(a, 0.f);
    }
    __syncthreads();
    if(t < EO){
        float a = b2[t];
        #pragma unroll
        for(int j=0;j<4;j++) a = fmaf(w2[t*4+j], r1[j], a);
        ss[t] = 1.f/(1.f + __expf(-a));
    }
    __syncthreads();
    // thread t = k-row of M_b:  M[k][hd] = sum_e embW[e][k]*s[e]*gatW[hd][e]
    float ew[EO];
    #pragma unroll
    for(int e=0;e<EO;e++) ew[e] = embW[e*Ln + t] * ss[e];
    #pragma unroll
    for(int hd=0; hd<EO; hd++){
        float a = 0.f;
        #pragma unroll
        for(int e=0;e<EO;e++) a = fmaf(ew[e], sgw[hd*EO+e], a);
        g_M[((size_t)b*Ln + t)*EO + hd] = a;
    }
    if(t < EO){
        float a = 0.f;
        #pragma unroll
        for(int e=0;e<EO;e++) a = fmaf(embB[e]*ss[e], sgw[t*EO+e], a);
        g_cb[b*EO + t] = a;
    }
}

// ---------------- feat = feature @ M_b + c_b  (pass 2 over feature) + el/er ----------------
__global__ void __launch_bounds__(256) k_feat(const float* __restrict__ feature,
                                              const float* __restrict__ al,
                                              const float* __restrict__ ar){
    __shared__ __align__(16) float sM[Ln*EO];    // 16 KB, k-major rows of 16
    __shared__ float sF[256*17];                 // 256 nodes x 16 k, pad 17
    __shared__ float sal[EO], sar[EO], scb[EO];
    int t  = threadIdx.x;
    int nb = blockIdx.x*256;
    int b  = nb >> 11;
    const float* Mp = &g_M[(size_t)b*Ln*EO];
    for(int i=t;i<Ln*EO;i+=256) sM[i] = Mp[i];
    if(t < EO){ sal[t]=al[t]; sar[t]=ar[t]; scb[t]=g_cb[b*EO+t]; }
    __syncthreads();

    float acc[EO];
    #pragma unroll
    for(int hd=0;hd<EO;hd++) acc[hd] = scb[hd];

    for(int kc=0; kc<16; kc++){
        const float* fp = feature + (size_t)nb*Ln + kc*16;
        for(int i=t;i<256*16;i+=256){
            int r = i>>4, c = i&15;
            sF[r*17 + c] = fp[(size_t)r*Ln + c];
        }
        __syncthreads();
        #pragma unroll
        for(int k=0;k<16;k++){
            float f = sF[t*17 + k];
            const float4* mp = (const float4*)(sM + ((kc<<4)+k)*EO);
            float4 m0=mp[0], m1=mp[1], m2=mp[2], m3=mp[3];
            acc[0]=fmaf(f,m0.x,acc[0]);   acc[1]=fmaf(f,m0.y,acc[1]);
            acc[2]=fmaf(f,m0.z,acc[2]);   acc[3]=fmaf(f,m0.w,acc[3]);
            acc[4]=fmaf(f,m1.x,acc[4]);   acc[5]=fmaf(f,m1.y,acc[5]);
            acc[6]=fmaf(f,m1.z,acc[6]);   acc[7]=fmaf(f,m1.w,acc[7]);
            acc[8]=fmaf(f,m2.x,acc[8]);   acc[9]=fmaf(f,m2.y,acc[9]);
            acc[10]=fmaf(f,m2.z,acc[10]); acc[11]=fmaf(f,m2.w,acc[11]);
            acc[12]=fmaf(f,m3.x,acc[12]); acc[13]=fmaf(f,m3.y,acc[13]);
            acc[14]=fmaf(f,m3.z,acc[14]); acc[15]=fmaf(f,m3.w,acc[15]);
        }
        __syncthreads();
    }
    int n = nb + t;
    float4* fo = (float4*)&g_feat[(size_t)n*EO];
    fo[0] = make_float4(acc[0],acc[1],acc[2],acc[3]);
    fo[1] = make_float4(acc[4],acc[5],acc[6],acc[7]);
    fo[2] = make_float4(acc[8],acc[9],acc[10],acc[11]);
    fo[3] = make_float4(acc[12],acc[13],acc[14],acc[15]);
    float el[Hn], er[Hn];
    #pragma unroll
    for(int h=0;h<Hn;h++){
        float a=0.f, bsum=0.f;
        #pragma unroll
        for(int d=0;d<4;d++){
            a    = fmaf(acc[h*4+d], sal[h*4+d], a);
            bsum = fmaf(acc[h*4+d], sar[h*4+d], bsum);
        }
        el[h]=a; er[h]=bsum;
    }
    *(float4*)&g_el[n*4] = make_float4(el[0],el[1],el[2],el[3]);
    *(float4*)&g_er[n*4] = make_float4(er[0],er[1],er[2],er[3]);
}

// ---------------- edge pass 1: segment max ----------------
__global__ void k_edge_max(const int* __restrict__ src, const int* __restrict__ dst){
    int i = blockIdx.x*256 + threadIdx.x;
    int s = src[i], d = dst[i];
    float4 l = *(const float4*)&g_el[s*4];
    float4 r = *(const float4*)&g_er[d*4];
    float v0=l.x+r.x, v1=l.y+r.y, v2=l.z+r.z, v3=l.w+r.w;
    v0 = v0>0.f?v0:0.2f*v0;  v1 = v1>0.f?v1:0.2f*v1;
    v2 = v2>0.f?v2:0.2f*v2;  v3 = v3>0.f?v3:0.2f*v3;
    atomicMax(&g_mord[d*4+0], f2ord(v0));
    atomicMax(&g_mord[d*4+1], f2ord(v1));
    atomicMax(&g_mord[d*4+2], f2ord(v2));
    atomicMax(&g_mord[d*4+3], f2ord(v3));
}

// ---------------- edge pass 2: exp + unnormalized aggregation ----------------
__global__ void k_edge_acc(const int* __restrict__ src, const int* __restrict__ dst){
    int i = blockIdx.x*256 + threadIdx.x;
    int s = src[i], d = dst[i];
    float4 l = *(const float4*)&g_el[s*4];
    float4 r = *(const float4*)&g_er[d*4];
    uint4  mo = *(const uint4*)&g_mord[d*4];
    float v[4]  = { l.x+r.x, l.y+r.y, l.z+r.z, l.w+r.w };
    float mm[4] = { ord2f(mo.x), ord2f(mo.y), ord2f(mo.z), ord2f(mo.w) };
    #pragma unroll
    for(int h=0;h<Hn;h++){
        float e  = v[h]>0.f ? v[h] : 0.2f*v[h];
        float ee = __expf(e - mm[h]);
        atomicAdd(&g_den[d*4+h], ee);
        float4 f = *(const float4*)&g_feat[(size_t)s*EO + h*4];
        atomicAdd(&g_acc[(size_t)d*EO + h*4 + 0], ee*f.x);
        atomicAdd(&g_acc[(size_t)d*EO + h*4 + 1], ee*f.y);
        atomicAdd(&g_acc[(size_t)d*EO + h*4 + 2], ee*f.z);
        atomicAdd(&g_acc[(size_t)d*EO + h*4 + 3], ee*f.w);
    }
}

// ---------------- normalize -> encode, fold proj/graph_W into pa/pb ----------------
__global__ void k_node(const float* __restrict__ gatB, const float* __restrict__ projW,
                       const float* __restrict__ projB, const float* __restrict__ graphW){
    int n = blockIdx.x*256 + threadIdx.x;
    float enc[EO];
    #pragma unroll
    for(int h=0;h<Hn;h++){
        float den = g_den[n*4+h];
        float inv = den > 0.f ? 1.f/den : 0.f;
        #pragma unroll
        for(int j=0;j<4;j++)
            enc[h*4+j] = g_acc[(size_t)n*EO + h*4 + j]*inv + gatB[h*4+j];
    }
    float4* eo = (float4*)&g_enc[(size_t)n*EO];
    eo[0] = make_float4(enc[0],enc[1],enc[2],enc[3]);
    eo[1] = make_float4(enc[4],enc[5],enc[6],enc[7]);
    eo[2] = make_float4(enc[8],enc[9],enc[10],enc[11]);
    eo[3] = make_float4(enc[12],enc[13],enc[14],enc[15]);
    float pa=0.f, pb=0.f;
    #pragma unroll
    for(int g=0;g<Gn;g++){
        float hp = projB[g];
        #pragma unroll
        for(int hd=0;hd<EO;hd++) hp = fmaf(projW[g*EO+hd], enc[hd], hp);
        pa = fmaf(hp, graphW[g],    pa);
        pb = fmaf(hp, graphW[Gn+g], pb);
    }
    g_pa[n]=pa; g_pb[n]=pb;
}

// ---------------- final: out = w*gram + (1-w)*(pa_i+pb_j) ----------------
__global__ void __launch_bounds__(256) k_out(const float* __restrict__ w,
                                             float* __restrict__ out){
    __shared__ __align__(16) float sA[16*132];
    __shared__ __align__(16) float sB[16*132];
    __shared__ float spa[128], spb[128];
    int b  = blockIdx.z;
    int i0 = blockIdx.y*128, j0 = blockIdx.x*128;
    int t  = threadIdx.x;
    const float* encA = &g_enc[((size_t)b*Cn + i0)*EO];
    const float* encB = &g_enc[((size_t)b*Cn + j0)*EO];
    for(int i=t;i<2048;i+=256){
        int k = i&15, r = i>>4;     // i == r*16 + k -> direct index
        sA[k*132 + r] = encA[i];
        sB[k*132 + r] = encB[i];
    }
    if(t < 128){ spa[t] = g_pa[b*Cn + i0 + t]; spb[t] = g_pb[b*Cn + j0 + t]; }
    __syncthreads();

    int tx = t & 15, ty = t >> 4;
    float acc[8][8];
    #pragma unroll
    for(int u=0;u<8;u++)
        #pragma unroll
        for(int v=0;v<8;v++) acc[u][v]=0.f;

    #pragma unroll
    for(int k=0;k<16;k++){
        const float* Ap = sA + k*132 + (ty<<3);
        const float* Bp = sB + k*132 + (tx<<3);
        float4 a0=*(const float4*)Ap,     a1=*(const float4*)(Ap+4);
        float4 b0=*(const float4*)Bp,     b1=*(const float4*)(Bp+4);
        float av[8]={a0.x,a0.y,a0.z,a0.w,a1.x,a1.y,a1.z,a1.w};
        float bv[8]={b0.x,b0.y,b0.z,b0.w,b1.x,b1.y,b1.z,b1.w};
        #pragma unroll
        for(int u=0;u<8;u++)
            #pragma unroll
            for(int v=0;v<8;v++) acc[u][v]=fmaf(av[u],bv[v],acc[u][v]);
    }

    float par[8], pbc[8];
    #pragma unroll
    for(int u=0;u<8;u++){ par[u]=spa[(ty<<3)+u]; pbc[u]=spb[(tx<<3)+u]; }

    const size_t ob = (size_t)b*Cn*Cn;
    #pragma unroll
    for(int u=0;u<8;u++){
        int i = i0 + (ty<<3) + u;
        const float* wr = w + (size_t)i*Cn + j0 + (tx<<3);
        float4 w0=*(const float4*)wr, w1=*(const float4*)(wr+4);
        float g2;
        float4 o0,o1;
        g2=par[u]+pbc[0]; o0.x=fmaf(w0.x, acc[u][0]-g2, g2);
        g2=par[u]+pbc[1]; o0.y=fmaf(w0.y, acc[u][1]-g2, g2);
        g2=par[u]+pbc[2]; o0.z=fmaf(w0.z, acc[u][2]-g2, g2);
        g2=par[u]+pbc[3]; o0.w=fmaf(w0.w, acc[u][3]-g2, g2);
        g2=par[u]+pbc[4]; o1.x=fmaf(w1.x, acc[u][4]-g2, g2);
        g2=par[u]+pbc[5]; o1.y=fmaf(w1.y, acc[u][5]-g2, g2);
        g2=par[u]+pbc[6]; o1.z=fmaf(w1.z, acc[u][6]-g2, g2);
        g2=par[u]+pbc[7]; o1.w=fmaf(w1.w, acc[u][7]-g2, g2);
        float* orow = out + ob + (size_t)i*Cn + j0 + (tx<<3);
        *(float4*)orow     = o0;
        *(float4*)(orow+4) = o1;
    }
}

// ---------------- launch ----------------
extern "C" void kernel_launch(void* const* d_in, const int* in_sizes, int n_in,
                              void* d_out, int out_size){
    const float* feature=(const float*)d_in[0];
    const int*   src    =(const int*)  d_in[1];
    const int*   dst    =(const int*)  d_in[2];
    const float* embW   =(const float*)d_in[3];
    const float* embB   =(const float*)d_in[4];
    const float* seW1   =(const float*)d_in[5];
    const float* seB1   =(const float*)d_in[6];
    const float* seW2   =(const float*)d_in[7];
    const float* seB2   =(const float*)d_in[8];
    const float* gatW   =(const float*)d_in[9];
    const float* al     =(const float*)d_in[10];
    const float* ar     =(const float*)d_in[11];
    const float* gatB   =(const float*)d_in[12];
    const float* projW  =(const float*)d_in[13];
    const float* projB  =(const float*)d_in[14];
    const float* graphW =(const float*)d_in[15];
    const float* w      =(const float*)d_in[16];
    float* out = (float*)d_out;

    k_init<<<(Nn*EO + 255)/256, 256>>>();
    k_fmean<<<dim3(64, Bn), 256>>>(feature);
    k_prep<<<Bn, 256>>>(embW, embB, seW1, seB1, seW2, seB2, gatW);
    k_feat<<<Nn/256, 256>>>(feature, al, ar);
    k_edge_max<<<NEn/256, 256>>>(src, dst);
    k_edge_acc<<<NEn/256, 256>>>(src, dst);
    k_node<<<Nn/256, 256>>>(gatB, projW, projB, graphW);
    k_out<<<dim3(Cn/128, Cn/128, Bn), 256>>>(w, out);
}

// round 3
// speedup vs baseline: 1.3843x; 1.3843x over previous
#include <cuda_runtime.h>
#include <math.h>

#define Bn 16
#define Cn 2048
#define Ln 256
#define EO 16
#define Hn 4
#define Gn 4
#define Nn (Bn*Cn)      /* 32768 */
#define NEn 524288

typedef unsigned long long ull;

// ---------------- scratch (device globals; no allocation) ----------------
__device__ __align__(16) float g_y[Nn*EO];       // emb output (incl emb_b)
__device__ __align__(16) float g_G[Bn*EO*EO];    // gatW * s  per batch
__device__ __align__(16) float g_feat[Nn*EO];
__device__ __align__(16) float g_el[Nn*Hn];
__device__ __align__(16) float g_er[Nn*Hn];
__device__ __align__(16) float g_den[Nn*Hn];
__device__ __align__(16) float g_acc[Nn*EO];
__device__ __align__(16) float g_enc[Nn*EO];
__device__ float g_pa[Nn];
__device__ float g_pb[Nn];

// ---------------- f32x2 helpers (Blackwell packed fp32) ----------------
__device__ __forceinline__ ull pack2(float lo, float hi){
    ull r; asm("mov.b64 %0, {%1, %2};" : "=l"(r) : "f"(lo), "f"(hi)); return r;
}
__device__ __forceinline__ void unpack2(ull v, float& lo, float& hi){
    asm("mov.b64 {%0, %1}, %2;" : "=f"(lo), "=f"(hi) : "l"(v));
}
__device__ __forceinline__ ull ffma2(ull a, ull b, ull c){
    ull d; asm("fma.rn.f32x2 %0, %1, %2, %3;" : "=l"(d) : "l"(a), "l"(b), "l"(c)); return d;
}
__device__ __forceinline__ void red4(float* p, float a, float b, float c, float d){
    asm volatile("red.global.add.v4.f32 [%0], {%1, %2, %3, %4};"
                 :: "l"(p), "f"(a), "f"(b), "f"(c), "f"(d) : "memory");
}

union F4U { float4 v; ull u[2]; };

// ---------------- init scratch (den + acc zeros) ----------------
__global__ void k_init(){
    int i = blockIdx.x*256 + threadIdx.x;
    float4 z = make_float4(0.f,0.f,0.f,0.f);
    if(i < Nn*Hn/4) ((float4*)g_den)[i] = z;
    ((float4*)g_acc)[i] = z;     // grid sized exactly to Nn*EO/4
}

// ---------------- single feature pass: y = feature @ embW^T + emb_b ----------------
// 4 threads per node (k-quarters of 64), shuffle reduce; no feature staging.
__global__ void __launch_bounds__(256) k_emb(const float* __restrict__ feature,
                                             const float* __restrict__ embW,
                                             const float* __restrict__ embB){
    __shared__ float sW[4*1028];   // quarter q at q*1028: 64 k-cols x 16 e (+4-word skew)
    int tid = threadIdx.x;
    for(int idx = tid; idx < Ln*EO; idx += 256){
        int e = idx >> 8, k = idx & 255;
        sW[(k>>6)*1028 + (k&63)*16 + e] = embW[e*Ln + k];
    }
    __syncthreads();

    int gtid = blockIdx.x*256 + tid;
    int node = gtid >> 2, q = gtid & 3;
    const float4* fp = (const float4*)(feature + (size_t)node*Ln + q*64);
    const float*  wq = sW + q*1028;

    ull acc2[8];
    #pragma unroll
    for(int g=0; g<8; g++) acc2[g] = 0ull;

    #pragma unroll
    for(int j=0; j<16; j++){
        float4 f = fp[j];
        float fv[4] = {f.x, f.y, f.z, f.w};
        #pragma unroll
        for(int i=0; i<4; i++){
            ull fd = pack2(fv[i], fv[i]);
            const float* wk = wq + (j*4+i)*16;
            F4U w0, w1, w2, w3;
            w0.v = *(const float4*)(wk);
            w1.v = *(const float4*)(wk+4);
            w2.v = *(const float4*)(wk+8);
            w3.v = *(const float4*)(wk+12);
            acc2[0] = ffma2(fd, w0.u[0], acc2[0]);
            acc2[1] = ffma2(fd, w0.u[1], acc2[1]);
            acc2[2] = ffma2(fd, w1.u[0], acc2[2]);
            acc2[3] = ffma2(fd, w1.u[1], acc2[3]);
            acc2[4] = ffma2(fd, w2.u[0], acc2[4]);
            acc2[5] = ffma2(fd, w2.u[1], acc2[5]);
            acc2[6] = ffma2(fd, w3.u[0], acc2[6]);
            acc2[7] = ffma2(fd, w3.u[1], acc2[7]);
        }
    }
    float acc[16];
    #pragma unroll
    for(int g=0; g<8; g++) unpack2(acc2[g], acc[2*g], acc[2*g+1]);
    #pragma unroll
    for(int e=0; e<16; e++){
        acc[e] += __shfl_xor_sync(0xffffffffu, acc[e], 1);
        acc[e] += __shfl_xor_sync(0xffffffffu, acc[e], 2);
    }
    float4 o;
    o.x = acc[q*4+0] + __ldg(&embB[q*4+0]);
    o.y = acc[q*4+1] + __ldg(&embB[q*4+1]);
    o.z = acc[q*4+2] + __ldg(&embB[q*4+2]);
    o.w = acc[q*4+3] + __ldg(&embB[q*4+3]);
    *(float4*)&g_y[(size_t)node*EO + q*4] = o;
}

// ---------------- per batch: z = mean(y), SE -> s, G_b = gatW * s ----------------
__global__ void k_zprep(const float* __restrict__ w1, const float* __restrict__ b1,
                        const float* __restrict__ w2, const float* __restrict__ b2,
                        const float* __restrict__ gatW){
    int b = blockIdx.x, t = threadIdx.x;
    __shared__ float sred[16*17];
    __shared__ float zs[16], r1[4], ss[16];
    int e = t & 15, part = t >> 4;
    const float* yp = g_y + ((size_t)b*Cn + part)*EO + e;
    float a = 0.f;
    for(int j=0; j<128; j++) a += yp[(size_t)j*16*EO];
    sred[part*17 + e] = a;
    __syncthreads();
    if(t < 16){
        float s2 = 0.f;
        #pragma unroll
        for(int p=0; p<16; p++) s2 += sred[p*17 + t];
        zs[t] = s2 * (1.0f/Cn);
    }
    __syncthreads();
    if(t < 4){
        float a1 = b1[t];
        #pragma unroll
        for(int ee=0; ee<16; ee++) a1 = fmaf(w1[t*16+ee], zs[ee], a1);
        r1[t] = fmaxf(a1, 0.f);
    }
    __syncthreads();
    if(t < 16){
        float a2 = b2[t];
        #pragma unroll
        for(int j=0; j<4; j++) a2 = fmaf(w2[t*4+j], r1[j], a2);
        ss[t] = 1.f/(1.f + __expf(-a2));
    }
    __syncthreads();
    g_G[b*256 + t] = gatW[t] * ss[t & 15];
}

// ---------------- feat = y_s @ gatW^T ; el, er ----------------
__global__ void __launch_bounds__(256) k_feat2(const float* __restrict__ al,
                                               const float* __restrict__ ar){
    __shared__ float sG[256];
    __shared__ float sal[16], sar[16];
    int t = threadIdx.x;
    int nb = blockIdx.x*256;
    int b = nb >> 11;
    sG[t] = g_G[b*256 + t];
    if(t < 16){ sal[t]=al[t]; sar[t]=ar[t]; }
    __syncthreads();

    int n = nb + t;
    const float4* yp = (const float4*)&g_y[(size_t)n*EO];
    float4 y0=yp[0], y1=yp[1], y2=yp[2], y3=yp[3];
    float yv[16] = {y0.x,y0.y,y0.z,y0.w, y1.x,y1.y,y1.z,y1.w,
                    y2.x,y2.y,y2.z,y2.w, y3.x,y3.y,y3.z,y3.w};
    float fe[16];
    #pragma unroll
    for(int hd=0; hd<16; hd++){
        const float4* gp = (const float4*)(sG + hd*16);
        float4 g0=gp[0], g1=gp[1], g2=gp[2], g3=gp[3];
        float a = 0.f;
        a = fmaf(g0.x,yv[0],a);  a = fmaf(g0.y,yv[1],a);
        a = fmaf(g0.z,yv[2],a);  a = fmaf(g0.w,yv[3],a);
        a = fmaf(g1.x,yv[4],a);  a = fmaf(g1.y,yv[5],a);
        a = fmaf(g1.z,yv[6],a);  a = fmaf(g1.w,yv[7],a);
        a = fmaf(g2.x,yv[8],a);  a = fmaf(g2.y,yv[9],a);
        a = fmaf(g2.z,yv[10],a); a = fmaf(g2.w,yv[11],a);
        a = fmaf(g3.x,yv[12],a); a = fmaf(g3.y,yv[13],a);
        a = fmaf(g3.z,yv[14],a); a = fmaf(g3.w,yv[15],a);
        fe[hd] = a;
    }
    float4* fo = (float4*)&g_feat[(size_t)n*EO];
    fo[0] = make_float4(fe[0],fe[1],fe[2],fe[3]);
    fo[1] = make_float4(fe[4],fe[5],fe[6],fe[7]);
    fo[2] = make_float4(fe[8],fe[9],fe[10],fe[11]);
    fo[3] = make_float4(fe[12],fe[13],fe[14],fe[15]);
    float el[4], er[4];
    #pragma unroll
    for(int h=0; h<4; h++){
        float a=0.f, c=0.f;
        #pragma unroll
        for(int d=0; d<4; d++){
            a = fmaf(fe[h*4+d], sal[h*4+d], a);
            c = fmaf(fe[h*4+d], sar[h*4+d], c);
        }
        el[h]=a; er[h]=c;
    }
    *(float4*)&g_el[n*4] = make_float4(el[0],el[1],el[2],el[3]);
    *(float4*)&g_er[n*4] = make_float4(er[0],er[1],er[2],er[3]);
}

// ---------------- single edge pass: exp (no max needed) + vector-red aggregation ----------------
__global__ void __launch_bounds__(256) k_edge(const int* __restrict__ src,
                                              const int* __restrict__ dst){
    int i = blockIdx.x*256 + threadIdx.x;
    int s = src[i], d = dst[i];
    float4 l = *(const float4*)&g_el[s*4];
    float4 r = *(const float4*)&g_er[d*4];
    float v0=l.x+r.x, v1=l.y+r.y, v2=l.z+r.z, v3=l.w+r.w;
    v0 = v0>0.f?v0:0.2f*v0;  v1 = v1>0.f?v1:0.2f*v1;
    v2 = v2>0.f?v2:0.2f*v2;  v3 = v3>0.f?v3:0.2f*v3;
    float e0=__expf(v0), e1=__expf(v1), e2=__expf(v2), e3=__expf(v3);
    red4(&g_den[d*4], e0, e1, e2, e3);
    const float4* fs = (const float4*)&g_feat[(size_t)s*EO];
    float4 f0=fs[0], f1=fs[1], f2=fs[2], f3=fs[3];
    red4(&g_acc[(size_t)d*EO + 0],  e0*f0.x, e0*f0.y, e0*f0.z, e0*f0.w);
    red4(&g_acc[(size_t)d*EO + 4],  e1*f1.x, e1*f1.y, e1*f1.z, e1*f1.w);
    red4(&g_acc[(size_t)d*EO + 8],  e2*f2.x, e2*f2.y, e2*f2.z, e2*f2.w);
    red4(&g_acc[(size_t)d*EO + 12], e3*f3.x, e3*f3.y, e3*f3.z, e3*f3.w);
}

// ---------------- normalize -> encode, fold proj/graph_W into pa/pb ----------------
__global__ void k_node(const float* __restrict__ gatB, const float* __restrict__ projW,
                       const float* __restrict__ projB, const float* __restrict__ graphW){
    int n = blockIdx.x*256 + threadIdx.x;
    float enc[EO];
    #pragma unroll
    for(int h=0; h<Hn; h++){
        float den = g_den[n*4+h];
        float inv = den > 0.f ? 1.f/den : 0.f;
        #pragma unroll
        for(int j=0; j<4; j++)
            enc[h*4+j] = g_acc[(size_t)n*EO + h*4 + j]*inv + gatB[h*4+j];
    }
    float4* eo = (float4*)&g_enc[(size_t)n*EO];
    eo[0] = make_float4(enc[0],enc[1],enc[2],enc[3]);
    eo[1] = make_float4(enc[4],enc[5],enc[6],enc[7]);
    eo[2] = make_float4(enc[8],enc[9],enc[10],enc[11]);
    eo[3] = make_float4(enc[12],enc[13],enc[14],enc[15]);
    float pa=0.f, pb=0.f;
    #pragma unroll
    for(int g=0; g<Gn; g++){
        float hp = projB[g];
        #pragma unroll
        for(int hd=0; hd<EO; hd++) hp = fmaf(projW[g*EO+hd], enc[hd], hp);
        pa = fmaf(hp, graphW[g],    pa);
        pb = fmaf(hp, graphW[Gn+g], pb);
    }
    g_pa[n]=pa; g_pb[n]=pb;
}

// ---------------- final: out = w*gram + (1-w)*(pa_i+pb_j), f32x2 FMA ----------------
__global__ void __launch_bounds__(256) k_out(const float* __restrict__ w,
                                             float* __restrict__ out){
    __shared__ __align__(16) float sA[16*132];
    __shared__ __align__(16) float sB[16*132];
    __shared__ float spa[128], spb[128];
    int b  = blockIdx.z;
    int i0 = blockIdx.y*128, j0 = blockIdx.x*128;
    int t  = threadIdx.x;
    const float* encA = &g_enc[((size_t)b*Cn + i0)*EO];
    const float* encB = &g_enc[((size_t)b*Cn + j0)*EO];
    for(int i=t; i<2048; i+=256){
        int k = i&15, r = i>>4;
        sA[k*132 + r] = encA[i];
        sB[k*132 + r] = encB[i];
    }
    if(t < 128){ spa[t] = g_pa[b*Cn + i0 + t]; spb[t] = g_pb[b*Cn + j0 + t]; }
    __syncthreads();

    int tx = t & 15, ty = t >> 4;
    ull acc2[8][4];
    #pragma unroll
    for(int u=0; u<8; u++)
        #pragma unroll
        for(int v=0; v<4; v++) acc2[u][v] = 0ull;

    #pragma unroll
    for(int k=0; k<16; k++){
        const float* Ap = sA + k*132 + (ty<<3);
        const float* Bp = sB + k*132 + (tx<<3);
        float4 a0 = *(const float4*)Ap, a1 = *(const float4*)(Ap+4);
        F4U b0, b1;
        b0.v = *(const float4*)Bp;  b1.v = *(const float4*)(Bp+4);
        float av[8] = {a0.x,a0.y,a0.z,a0.w, a1.x,a1.y,a1.z,a1.w};
        ull bp[4] = {b0.u[0], b0.u[1], b1.u[0], b1.u[1]};
        #pragma unroll
        for(int u=0; u<8; u++){
            ull ad = pack2(av[u], av[u]);
            acc2[u][0] = ffma2(ad, bp[0], acc2[u][0]);
            acc2[u][1] = ffma2(ad, bp[1], acc2[u][1]);
            acc2[u][2] = ffma2(ad, bp[2], acc2[u][2]);
            acc2[u][3] = ffma2(ad, bp[3], acc2[u][3]);
        }
    }

    float par[8], pbc[8];
    #pragma unroll
    for(int u=0; u<8; u++){ par[u]=spa[(ty<<3)+u]; pbc[u]=spb[(tx<<3)+u]; }

    const size_t ob = (size_t)b*Cn*Cn;
    #pragma unroll
    for(int u=0; u<8; u++){
        float acc[8];
        #pragma unroll
        for(int v=0; v<4; v++) unpack2(acc2[u][v], acc[2*v], acc[2*v+1]);
        int i = i0 + (ty<<3) + u;
        const float* wr = w + (size_t)i*Cn + j0 + (tx<<3);
        float4 w0=*(const float4*)wr, w1=*(const float4*)(wr+4);
        float g2;
        float4 o0, o1;
        g2=par[u]+pbc[0]; o0.x=fmaf(w0.x, acc[0]-g2, g2);
        g2=par[u]+pbc[1]; o0.y=fmaf(w0.y, acc[1]-g2, g2);
        g2=par[u]+pbc[2]; o0.z=fmaf(w0.z, acc[2]-g2, g2);
        g2=par[u]+pbc[3]; o0.w=fmaf(w0.w, acc[3]-g2, g2);
        g2=par[u]+pbc[4]; o1.x=fmaf(w1.x, acc[4]-g2, g2);
        g2=par[u]+pbc[5]; o1.y=fmaf(w1.y, acc[5]-g2, g2);
        g2=par[u]+pbc[6]; o1.z=fmaf(w1.z, acc[6]-g2, g2);
        g2=par[u]+pbc[7]; o1.w=fmaf(w1.w, acc[7]-g2, g2);
        float* orow = out + ob + (size_t)i*Cn + j0 + (tx<<3);
        *(float4*)orow     = o0;
        *(float4*)(orow+4) = o1;
    }
}

// ---------------- launch ----------------
extern "C" void kernel_launch(void* const* d_in, const int* in_sizes, int n_in,
                              void* d_out, int out_size){
    const float* feature=(const float*)d_in[0];
    const int*   src    =(const int*)  d_in[1];
    const int*   dst    =(const int*)  d_in[2];
    const float* embW   =(const float*)d_in[3];
    const float* embB   =(const float*)d_in[4];
    const float* seW1   =(const float*)d_in[5];
    const float* seB1   =(const float*)d_in[6];
    const float* seW2   =(const float*)d_in[7];
    const float* seB2   =(const float*)d_in[8];
    const float* gatW   =(const float*)d_in[9];
    const float* al     =(const float*)d_in[10];
    const float* ar     =(const float*)d_in[11];
    const float* gatB   =(const float*)d_in[12];
    const float* projW  =(const float*)d_in[13];
    const float* projB  =(const float*)d_in[14];
    const float* graphW =(const float*)d_in[15];
    const float* wmat   =(const float*)d_in[16];
    float* out = (float*)d_out;

    k_init<<<(Nn*EO/4)/256, 256>>>();
    k_emb<<<(Nn*4)/256, 256>>>(feature, embW, embB);
    k_zprep<<<Bn, 256>>>(seW1, seB1, seW2, seB2, gatW);
    k_feat2<<<Nn/256, 256>>>(al, ar);
    k_edge<<<NEn/256, 256>>>(src, dst);
    k_node<<<Nn/256, 256>>>(gatB, projW, projB, graphW);
    k_out<<<dim3(Cn/128, Cn/128, Bn), 256>>>(wmat, out);
}